// round 12
// baseline (speedup 1.0000x reference)
#include <cuda_runtime.h>
#include <cuda_bf16.h>
#include <cstdint>

// Problem constants
#define Bsz 8192
#define Kc  25
#define Lc  25
#define BN_EPS 1e-5f

typedef unsigned long long ull;

// Scratch (device globals — no allocations allowed)
__device__ float g_xnT[Lc * Bsz];   // transposed normalized input: [l][b]
__device__ float g_s[Lc];
__device__ float g_t[Lc];

// ---------- packed f32x2 helpers ----------
__device__ __forceinline__ ull pk2(float lo, float hi) {
    ull r;
    asm("mov.b64 %0, {%1, %2};" : "=l"(r) : "f"(lo), "f"(hi));
    return r;
}
__device__ __forceinline__ void unpk2(ull v, float& lo, float& hi) {
    asm("mov.b64 {%0, %1}, %2;" : "=f"(lo), "=f"(hi) : "l"(v));
}
__device__ __forceinline__ ull fma2(ull a, ull b, ull c) {
    ull d;
    asm("fma.rn.f32x2 %0, %1, %2, %3;" : "=l"(d) : "l"(a), "l"(b), "l"(c));
    return d;
}
__device__ __forceinline__ ull add2(ull a, ull b) {
    ull d;
    asm("add.rn.f32x2 %0, %1, %2;" : "=l"(d) : "l"(a), "l"(b));
    return d;
}
__device__ __forceinline__ ull relu2(ull v) {
    float lo, hi;
    unpk2(v, lo, hi);
    lo = fmaxf(lo, 0.0f);
    hi = fmaxf(hi, 0.0f);
    return pk2(lo, hi);
}

// ---------- Kernel 1: BatchNorm statistics (one block per column l) ----------
__global__ void bn_stats_kernel(const float* __restrict__ x,
                                const float* __restrict__ gamma,
                                const float* __restrict__ bn_bias) {
    const int l = blockIdx.x;
    const int t = threadIdx.x;
    float s = 0.0f, s2 = 0.0f;
    for (int b = t; b < Bsz; b += 256) {
        float v = x[b * Lc + l];
        s  += v;
        s2 += v * v;
    }
    __shared__ float sh[256], sh2[256];
    sh[t] = s; sh2[t] = s2;
    __syncthreads();
    for (int o = 128; o > 0; o >>= 1) {
        if (t < o) { sh[t] += sh[t + o]; sh2[t] += sh2[t + o]; }
        __syncthreads();
    }
    if (t == 0) {
        float mean = sh[0] * (1.0f / Bsz);
        float var  = sh2[0] * (1.0f / Bsz) - mean * mean;
        float sc   = gamma[l] * rsqrtf(var + BN_EPS);
        g_s[l] = sc;
        g_t[l] = bn_bias[l] - mean * sc;
    }
}

// ---------- Kernel 2: normalize + transpose to [l][b] ----------
__global__ void normt_kernel(const float* __restrict__ x) {
    const int e = blockIdx.x * blockDim.x + threadIdx.x;  // exactly B*L threads
    const int b = e / Lc;
    const int l = e - b * Lc;
    g_xnT[l * Bsz + b] = fmaf(x[e], g_s[l], g_t[l]);
}

// ---------- Kernel 3: MLP stack ----------
// grid = (16 b-chunks, 25 k), block = 128 threads.
// Each thread handles 4 consecutive b (2 packed f32x2 pairs).
// smem layout per l (150 duplicated pairs, 1200 B):
//   [0..8)    w1[h]
//   [8..16)   b1[h]
//   [16..80)  w2[i*8+h]
//   [80..88)  b2[i]
//   [88..136) w3[j*8+i]
//   [136..142) b3[j]
//   [142..148) w4'[j] = alpha[l,k]*W4[j]
//   [148]     b4' = alpha[l,k]*b4 ;  [149] pad
__global__ void __launch_bounds__(128)
mlp_kernel(const float* __restrict__ W1, const float* __restrict__ b1,
           const float* __restrict__ W2, const float* __restrict__ b2,
           const float* __restrict__ W3, const float* __restrict__ b3,
           const float* __restrict__ W4, const float* __restrict__ b4,
           const float* __restrict__ alpha, const float* __restrict__ beta,
           float* __restrict__ out) {
    __shared__ __align__(16) ull wsm[Lc * 150];

    const int t = threadIdx.x;
    const int k = blockIdx.y;

    // ---- fill duplicated-packed weights for this k (all 25 l) ----
    for (int s = t; s < Lc * 150; s += 128) {
        const int l = s / 150;
        const int r = s - l * 150;
        const int kl = k * Lc + l;
        float v;
        if (r < 8)        v = W1[kl * 8 + r];
        else if (r < 16)  v = b1[kl * 8 + (r - 8)];
        else if (r < 80)  v = W2[kl * 64 + (r - 16)];
        else if (r < 88)  v = b2[kl * 8 + (r - 80)];
        else if (r < 136) v = W3[kl * 48 + (r - 88)];
        else if (r < 142) v = b3[kl * 6 + (r - 136)];
        else if (r < 148) v = alpha[l * Kc + k] * W4[kl * 6 + (r - 142)];
        else if (r == 148) v = alpha[l * Kc + k] * b4[kl];
        else              v = 0.0f;
        const unsigned int ub = __float_as_uint(v);
        wsm[s] = ((ull)ub << 32) | (ull)ub;
    }
    __syncthreads();

    const int boff = blockIdx.x * 512 + 4 * t;  // 4 consecutive b per thread
    const float bk = beta[k];
    ull acc0 = pk2(bk, bk);
    ull acc1 = acc0;

#pragma unroll 1
    for (int l = 0; l < Lc; ++l) {
        const ull* wp = wsm + l * 150;

        const float4 xv = *reinterpret_cast<const float4*>(&g_xnT[l * Bsz + boff]);
        const ull x0 = pk2(xv.x, xv.y);
        const ull x1 = pk2(xv.z, xv.w);

        // Layer 1: 1 -> 8
        ull h1a[8], h1b[8];
#pragma unroll
        for (int h = 0; h < 8; ++h) {
            const ull w  = wp[h];
            const ull bb = wp[8 + h];
            h1a[h] = relu2(fma2(w, x0, bb));
            h1b[h] = relu2(fma2(w, x1, bb));
        }

        // Layer 2: 8 -> 8
        ull h2a[8], h2b[8];
#pragma unroll
        for (int i = 0; i < 8; ++i) {
            ull t0 = wp[80 + i];
            ull t1 = t0;
#pragma unroll
            for (int h = 0; h < 8; ++h) {
                const ull w = wp[16 + i * 8 + h];
                t0 = fma2(w, h1a[h], t0);
                t1 = fma2(w, h1b[h], t1);
            }
            h2a[i] = relu2(t0);
            h2b[i] = relu2(t1);
        }

        // Layer 3: 8 -> 6
        ull h3a[6], h3b[6];
#pragma unroll
        for (int j = 0; j < 6; ++j) {
            ull t0 = wp[136 + j];
            ull t1 = t0;
#pragma unroll
            for (int i = 0; i < 8; ++i) {
                const ull w = wp[88 + j * 8 + i];
                t0 = fma2(w, h2a[i], t0);
                t1 = fma2(w, h2b[i], t1);
            }
            h3a[j] = relu2(t0);
            h3b[j] = relu2(t1);
        }

        // Layer 4 (+ folded alpha): 6 -> 1, accumulate over l
        acc0 = add2(acc0, wp[148]);
        acc1 = add2(acc1, wp[148]);
#pragma unroll
        for (int j = 0; j < 6; ++j) {
            const ull w = wp[142 + j];
            acc0 = fma2(w, h3a[j], acc0);
            acc1 = fma2(w, h3b[j], acc1);
        }
    }

    float o0, o1, o2, o3;
    unpk2(acc0, o0, o1);
    unpk2(acc1, o2, o3);
    out[(boff + 0) * Kc + k] = o0;
    out[(boff + 1) * Kc + k] = o1;
    out[(boff + 2) * Kc + k] = o2;
    out[(boff + 3) * Kc + k] = o3;
}

extern "C" void kernel_launch(void* const* d_in, const int* in_sizes, int n_in,
                              void* d_out, int out_size) {
    const float* x       = (const float*)d_in[0];
    const float* gamma   = (const float*)d_in[1];
    const float* bn_bias = (const float*)d_in[2];
    const float* W1      = (const float*)d_in[3];
    const float* b1      = (const float*)d_in[4];
    const float* W2      = (const float*)d_in[5];
    const float* b2      = (const float*)d_in[6];
    const float* W3      = (const float*)d_in[7];
    const float* b3      = (const float*)d_in[8];
    const float* W4      = (const float*)d_in[9];
    const float* b4      = (const float*)d_in[10];
    const float* alpha   = (const float*)d_in[11];
    const float* beta    = (const float*)d_in[12];
    float* out = (float*)d_out;

    bn_stats_kernel<<<Lc, 256>>>(x, gamma, bn_bias);
    normt_kernel<<<(Bsz * Lc) / 256, 256>>>(x);
    mlp_kernel<<<dim3(16, Kc), 128>>>(W1, b1, W2, b2, W3, b3, W4, b4,
                                      alpha, beta, out);
}

// round 13
// speedup vs baseline: 1.0821x; 1.0821x over previous
#include <cuda_runtime.h>
#include <cuda_bf16.h>
#include <cstdint>

// Problem constants
#define Bsz 8192
#define Kc  25
#define Lc  25
#define BN_EPS 1e-5f

typedef unsigned long long ull;

// Scratch (device globals — no allocations allowed)
__device__ float g_xnT[Lc * Bsz];   // transposed normalized input: [l][b]
__device__ float g_ps [Lc * 16];    // partial sums  per (l, chunk)
__device__ float g_ps2[Lc * 16];    // partial sum-of-squares

// ---------- packed f32x2 helpers ----------
__device__ __forceinline__ ull pk2(float lo, float hi) {
    ull r;
    asm("mov.b64 %0, {%1, %2};" : "=l"(r) : "f"(lo), "f"(hi));
    return r;
}
__device__ __forceinline__ void unpk2(ull v, float& lo, float& hi) {
    asm("mov.b64 {%0, %1}, %2;" : "=f"(lo), "=f"(hi) : "l"(v));
}
__device__ __forceinline__ ull fma2(ull a, ull b, ull c) {
    ull d;
    asm("fma.rn.f32x2 %0, %1, %2, %3;" : "=l"(d) : "l"(a), "l"(b), "l"(c));
    return d;
}
__device__ __forceinline__ ull add2(ull a, ull b) {
    ull d;
    asm("add.rn.f32x2 %0, %1, %2;" : "=l"(d) : "l"(a), "l"(b));
    return d;
}
__device__ __forceinline__ ull relu2(ull v) {
    float lo, hi;
    unpk2(v, lo, hi);
    lo = fmaxf(lo, 0.0f);
    hi = fmaxf(hi, 0.0f);
    return pk2(lo, hi);
}

// ---------- Kernel 1: BN partial sums ----------
// grid (16 chunks, 25 l), 128 threads. Each block reduces 512 rows of column l.
// Deterministic: fixed partial slot per (l, chunk).
__global__ void __launch_bounds__(128)
bn_partial_kernel(const float* __restrict__ x) {
    const int l = blockIdx.y;
    const int c = blockIdx.x;
    const int t = threadIdx.x;

    float s = 0.0f, s2 = 0.0f;
    const int base = c * 512;
#pragma unroll
    for (int i = 0; i < 4; ++i) {
        float v = x[(base + i * 128 + t) * Lc + l];
        s  += v;
        s2 += v * v;
    }
#pragma unroll
    for (int o = 16; o > 0; o >>= 1) {
        s  += __shfl_xor_sync(0xffffffffu, s,  o);
        s2 += __shfl_xor_sync(0xffffffffu, s2, o);
    }
    __shared__ float wa[4], wb[4];
    if ((t & 31) == 0) { wa[t >> 5] = s; wb[t >> 5] = s2; }
    __syncthreads();
    if (t == 0) {
        g_ps [l * 16 + c] = wa[0] + wa[1] + wa[2] + wa[3];
        g_ps2[l * 16 + c] = wb[0] + wb[1] + wb[2] + wb[3];
    }
}

// ---------- Kernel 2: finalize BN + normalize + transpose ----------
// grid 64 blocks x 128 threads; block handles 128 contiguous rows.
// Coalesced reads, smem-tiled transpose, coalesced column writes.
__global__ void __launch_bounds__(128)
normt_kernel(const float* __restrict__ x,
             const float* __restrict__ gamma,
             const float* __restrict__ bn_bias) {
    __shared__ float sh_s[Lc], sh_t[Lc];
    __shared__ float tile[128 * Lc];

    const int t  = threadIdx.x;
    const int rb = blockIdx.x * 128;          // first row of this tile

    // finalize BN stats (redundant per block; 25 threads, trivial cost)
    if (t < Lc) {
        float s = 0.0f, s2 = 0.0f;
#pragma unroll
        for (int c = 0; c < 16; ++c) {
            s  += g_ps [t * 16 + c];
            s2 += g_ps2[t * 16 + c];
        }
        float mean = s * (1.0f / Bsz);
        float var  = s2 * (1.0f / Bsz) - mean * mean;
        float sc   = gamma[t] * rsqrtf(var + BN_EPS);
        sh_s[t] = sc;
        sh_t[t] = bn_bias[t] - mean * sc;
    }

    // coalesced tile load: 128 rows * 25 cols = 3200 floats
    const float* xb = x + rb * Lc;
#pragma unroll
    for (int i = 0; i < Lc; ++i)
        tile[i * 128 + t] = xb[i * 128 + t];
    __syncthreads();

    // column writes: lane stride 25 in smem (gcd(25,32)=1 -> conflict-free),
    // 512B coalesced runs to global
#pragma unroll
    for (int l = 0; l < Lc; ++l)
        g_xnT[l * Bsz + rb + t] = fmaf(tile[t * Lc + l], sh_s[l], sh_t[l]);
}

// ---------- Kernel 3: MLP stack ----------
// grid = (16 b-chunks, 25 k), block = 128 threads.
// Each thread handles 4 consecutive b (2 packed f32x2 pairs).
// smem layout per l (150 duplicated pairs, 1200 B, 16B-aligned rows):
//   [0..8)    w1[h]      [8..16)   b1[h]
//   [16..80)  w2[i*8+h]  [80..88)  b2[i]
//   [88..136) w3[j*8+i]  [136..142) b3[j]
//   [142..148) w4'[j]=alpha*W4[j]  [148] b4'=alpha*b4  [149] pad
__global__ void __launch_bounds__(128)
mlp_kernel(const float* __restrict__ W1, const float* __restrict__ b1,
           const float* __restrict__ W2, const float* __restrict__ b2,
           const float* __restrict__ W3, const float* __restrict__ b3,
           const float* __restrict__ W4, const float* __restrict__ b4,
           const float* __restrict__ alpha, const float* __restrict__ beta,
           float* __restrict__ out) {
    __shared__ __align__(16) ull wsm[Lc * 150];

    const int t = threadIdx.x;
    const int k = blockIdx.y;

    // ---- fill duplicated-packed weights for this k (all 25 l) ----
    for (int s = t; s < Lc * 150; s += 128) {
        const int l = s / 150;
        const int r = s - l * 150;
        const int kl = k * Lc + l;
        float v;
        if (r < 8)        v = W1[kl * 8 + r];
        else if (r < 16)  v = b1[kl * 8 + (r - 8)];
        else if (r < 80)  v = W2[kl * 64 + (r - 16)];
        else if (r < 88)  v = b2[kl * 8 + (r - 80)];
        else if (r < 136) v = W3[kl * 48 + (r - 88)];
        else if (r < 142) v = b3[kl * 6 + (r - 136)];
        else if (r < 148) v = alpha[l * Kc + k] * W4[kl * 6 + (r - 142)];
        else if (r == 148) v = alpha[l * Kc + k] * b4[kl];
        else              v = 0.0f;
        const unsigned int ub = __float_as_uint(v);
        wsm[s] = ((ull)ub << 32) | (ull)ub;
    }
    __syncthreads();

    const int boff = blockIdx.x * 512 + 4 * t;  // 4 consecutive b per thread
    const float bk = beta[k];
    ull acc0 = pk2(bk, bk);
    ull acc1 = acc0;

    // software prefetch of x for l=0
    float4 xv = *reinterpret_cast<const float4*>(&g_xnT[boff]);

#pragma unroll 1
    for (int l = 0; l < Lc; ++l) {
        const ull* wp = wsm + l * 150;
        const ulonglong2* wq = reinterpret_cast<const ulonglong2*>(wp);

        const ull x0 = pk2(xv.x, xv.y);
        const ull x1 = pk2(xv.z, xv.w);
        if (l + 1 < Lc)   // prefetch next l (L2 latency hidden behind compute)
            xv = *reinterpret_cast<const float4*>(&g_xnT[(l + 1) * Bsz + boff]);

        // Layer 1: 1 -> 8   (4x v2 weight loads + 4x v2 bias loads)
        ull h1a[8], h1b[8];
#pragma unroll
        for (int hh = 0; hh < 4; ++hh) {
            const ulonglong2 w  = wq[hh];
            const ulonglong2 bb = wq[4 + hh];
            h1a[2 * hh]     = relu2(fma2(w.x, x0, bb.x));
            h1b[2 * hh]     = relu2(fma2(w.x, x1, bb.x));
            h1a[2 * hh + 1] = relu2(fma2(w.y, x0, bb.y));
            h1b[2 * hh + 1] = relu2(fma2(w.y, x1, bb.y));
        }

        // Layer 2: 8 -> 8  (rows processed in pairs so b2 loads are v2 too)
        ull h2a[8], h2b[8];
#pragma unroll
        for (int ii = 0; ii < 4; ++ii) {
            const ulonglong2 bb = wq[40 + ii];   // b2[2ii], b2[2ii+1]
            ull t0 = bb.x, t1 = bb.x, u0 = bb.y, u1 = bb.y;
#pragma unroll
            for (int hh = 0; hh < 4; ++hh) {
                const ulonglong2 wA = wq[8 + (2 * ii) * 4 + hh];
                const ulonglong2 wB = wq[8 + (2 * ii + 1) * 4 + hh];
                t0 = fma2(wA.x, h1a[2 * hh], t0);
                t0 = fma2(wA.y, h1a[2 * hh + 1], t0);
                t1 = fma2(wA.x, h1b[2 * hh], t1);
                t1 = fma2(wA.y, h1b[2 * hh + 1], t1);
                u0 = fma2(wB.x, h1a[2 * hh], u0);
                u0 = fma2(wB.y, h1a[2 * hh + 1], u0);
                u1 = fma2(wB.x, h1b[2 * hh], u1);
                u1 = fma2(wB.y, h1b[2 * hh + 1], u1);
            }
            h2a[2 * ii]     = relu2(t0);
            h2b[2 * ii]     = relu2(t1);
            h2a[2 * ii + 1] = relu2(u0);
            h2b[2 * ii + 1] = relu2(u1);
        }

        // Layer 3: 8 -> 6  (rows in pairs, b3 loads v2)
        ull h3a[6], h3b[6];
#pragma unroll
        for (int jj = 0; jj < 3; ++jj) {
            const ulonglong2 bb = wq[68 + jj];   // b3[2jj], b3[2jj+1]
            ull t0 = bb.x, t1 = bb.x, u0 = bb.y, u1 = bb.y;
#pragma unroll
            for (int hh = 0; hh < 4; ++hh) {
                const ulonglong2 wA = wq[44 + (2 * jj) * 4 + hh];
                const ulonglong2 wB = wq[44 + (2 * jj + 1) * 4 + hh];
                t0 = fma2(wA.x, h2a[2 * hh], t0);
                t0 = fma2(wA.y, h2a[2 * hh + 1], t0);
                t1 = fma2(wA.x, h2b[2 * hh], t1);
                t1 = fma2(wA.y, h2b[2 * hh + 1], t1);
                u0 = fma2(wB.x, h2a[2 * hh], u0);
                u0 = fma2(wB.y, h2a[2 * hh + 1], u0);
                u1 = fma2(wB.x, h2b[2 * hh], u1);
                u1 = fma2(wB.y, h2b[2 * hh + 1], u1);
            }
            h3a[2 * jj]     = relu2(t0);
            h3b[2 * jj]     = relu2(t1);
            h3a[2 * jj + 1] = relu2(u0);
            h3b[2 * jj + 1] = relu2(u1);
        }

        // Layer 4 (+ folded alpha): 6 -> 1, accumulate over l
        const ull c4 = wp[148];
        acc0 = add2(acc0, c4);
        acc1 = add2(acc1, c4);
#pragma unroll
        for (int jj = 0; jj < 3; ++jj) {
            const ulonglong2 w = wq[71 + jj];    // w4'[2jj], w4'[2jj+1]
            acc0 = fma2(w.x, h3a[2 * jj], acc0);
            acc0 = fma2(w.y, h3a[2 * jj + 1], acc0);
            acc1 = fma2(w.x, h3b[2 * jj], acc1);
            acc1 = fma2(w.y, h3b[2 * jj + 1], acc1);
        }
    }

    float o0, o1, o2, o3;
    unpk2(acc0, o0, o1);
    unpk2(acc1, o2, o3);
    out[(boff + 0) * Kc + k] = o0;
    out[(boff + 1) * Kc + k] = o1;
    out[(boff + 2) * Kc + k] = o2;
    out[(boff + 3) * Kc + k] = o3;
}

extern "C" void kernel_launch(void* const* d_in, const int* in_sizes, int n_in,
                              void* d_out, int out_size) {
    const float* x       = (const float*)d_in[0];
    const float* gamma   = (const float*)d_in[1];
    const float* bn_bias = (const float*)d_in[2];
    const float* W1      = (const float*)d_in[3];
    const float* b1      = (const float*)d_in[4];
    const float* W2      = (const float*)d_in[5];
    const float* b2      = (const float*)d_in[6];
    const float* W3      = (const float*)d_in[7];
    const float* b3      = (const float*)d_in[8];
    const float* W4      = (const float*)d_in[9];
    const float* b4      = (const float*)d_in[10];
    const float* alpha   = (const float*)d_in[11];
    const float* beta    = (const float*)d_in[12];
    float* out = (float*)d_out;

    bn_partial_kernel<<<dim3(16, Lc), 128>>>(x);
    normt_kernel<<<64, 128>>>(x, gamma, bn_bias);
    mlp_kernel<<<dim3(16, Kc), 128>>>(W1, b1, W2, b2, W3, b3, W4, b4,
                                      alpha, beta, out);
}